// round 15
// baseline (speedup 1.0000x reference)
#include <cuda_runtime.h>
#include <stdint.h>

#define NUM_EXPERTS 8
#define BATCH 4096
#define DM 1024
#define VOCAB 32000

#define TM 128                  // rows per chunk = BM
#define BN 128                  // CTA cols (halved: 2 CTAs/SM)
#define BK 32
#define NKI (DM / BK)           // 32 k-iterations
#define MAXC 40                 // max chunks: 4096/128 + 8 pad
#define XSROWS (MAXC * TM)      // 5120 padded rows
#define THREADS 128             // 4 warps: 2m x 2n, warp tile 64x64

// ---------------- device scratch (no allocations allowed) ----------------
__device__ int g_rows[BATCH];
__device__ int g_offsets[NUM_EXPERTS + 1];
__device__ int g_chunk_e[MAXC];
__device__ int g_chunk_pm0[MAXC];
__device__ int g_chunk_rows[MAXC];   // valid rows in this chunk (1..128)
__device__ int g_nchunks;
__device__ int g_prow[XSROWS];
__device__ float g_xs[(size_t)XSROWS * DM];  // tf32-rounded gathered x

// ---------------------------------------------------------------------------
// Kernel 1: group rows by expert (ptr % 8), build padded 128-row chunk table.
// Pointer dtype auto-detect (JAX x64-off downcasts int64->int32), as in R3.
// ---------------------------------------------------------------------------
__global__ void group_rows_kernel(const uint32_t* __restrict__ ptr_words) {
    __shared__ int counts[NUM_EXPERTS];
    __shared__ int cursor[NUM_EXPERTS];
    __shared__ int pad_off[NUM_EXPERTS];
    __shared__ int odd_nonzero;
    const int tid = threadIdx.x;

    if (tid == 0) odd_nonzero = 0;
    if (tid < NUM_EXPERTS) counts[tid] = 0;
    __syncthreads();

    int local_nz = 0;
    for (int i = tid; i < BATCH / 2; i += blockDim.x)
        if (ptr_words[2 * i + 1] != 0u) local_nz = 1;
    if (local_nz) atomicOr(&odd_nonzero, 1);
    __syncthreads();
    const bool is_i64 = (odd_nonzero == 0);

    for (int i = tid; i < BATCH; i += blockDim.x) {
        uint32_t v = is_i64 ? ptr_words[2 * i] : ptr_words[i];
        atomicAdd(&counts[v & (NUM_EXPERTS - 1)], 1);
    }
    __syncthreads();
    if (tid == 0) {
        int acc = 0, nc = 0, pbase = 0;
        for (int e = 0; e < NUM_EXPERTS; e++) {
            g_offsets[e] = acc;
            cursor[e] = acc;
            pad_off[e] = pbase;
            int cnt = counts[e];
            int nch = (cnt + TM - 1) / TM;
            for (int j = 0; j < nch; j++) {
                g_chunk_e[nc] = e;
                g_chunk_pm0[nc] = pbase + j * TM;
                int rem = cnt - j * TM;
                g_chunk_rows[nc] = rem > TM ? TM : rem;
                nc++;
            }
            pbase += nch * TM;
            acc += cnt;
        }
        g_offsets[NUM_EXPERTS] = acc;
        g_nchunks = nc;
    }
    __syncthreads();
    for (int i = tid; i < XSROWS; i += blockDim.x) g_prow[i] = -1;
    for (int i = tid; i < BATCH; i += blockDim.x) {
        uint32_t v = is_i64 ? ptr_words[2 * i] : ptr_words[i];
        int pos = atomicAdd(&cursor[v & (NUM_EXPERTS - 1)], 1);
        g_rows[pos] = i;
    }
    __syncthreads();
    for (int i = tid; i < BATCH; i += blockDim.x) {
        int e = 0;
        while (!(i >= g_offsets[e] && i < g_offsets[e + 1])) e++;
        g_prow[pad_off[e] + (i - g_offsets[e])] = g_rows[i];
    }
}

// ---------------------------------------------------------------------------
// Kernel 2: gather + RN-round x rows to tf32 into padded buffer (zeros pad).
// ---------------------------------------------------------------------------
__device__ __forceinline__ float to_tf32_rn(float v) {
    uint32_t b;
    asm("cvt.rna.tf32.f32 %0, %1;" : "=r"(b) : "f"(v));
    return __uint_as_float(b);
}
__device__ __forceinline__ uint32_t cvt_tf32_bits(float v) {
    uint32_t b;
    asm("cvt.rna.tf32.f32 %0, %1;" : "=r"(b) : "f"(v));
    return b;
}

__global__ void pack_kernel(const float* __restrict__ x) {
    const int p = blockIdx.x;
    const int r = g_prow[p];
    float4* dst = reinterpret_cast<float4*>(g_xs + (size_t)p * DM);
    if (r >= 0) {
        const float4* src = reinterpret_cast<const float4*>(x + (size_t)r * DM);
        for (int i = threadIdx.x; i < DM / 4; i += blockDim.x) {
            float4 v = src[i];
            v.x = to_tf32_rn(v.x); v.y = to_tf32_rn(v.y);
            v.z = to_tf32_rn(v.z); v.w = to_tf32_rn(v.w);
            dst[i] = v;
        }
    } else {
        float4 z = make_float4(0.f, 0.f, 0.f, 0.f);
        for (int i = threadIdx.x; i < DM / 4; i += blockDim.x) dst[i] = z;
    }
}

// ---------------------------------------------------------------------------
// Kernel 3: tf32 mma.sync GEMM, 2 CTAs/SM (decoupled barrier domains).
// CTA = 128 rows x 128 cols, 4 warps (2m x 2n), warp tile 64x64 (identical
// to champion). BK=32 double-buffered smem, register staging (4 A-units +
// 4 B-units per thread), in-loop B cvt (champion config), zero-row MMA
// elimination at 16-row granularity. 66 KB smem + <=255 regs => occupancy 2:
// one CTA's barrier/epilogue stalls are covered by the co-resident CTA.
// ---------------------------------------------------------------------------
__device__ __forceinline__ void mma_tf32(float& d0, float& d1, float& d2, float& d3,
                                         uint32_t a0, uint32_t a1, uint32_t a2, uint32_t a3,
                                         uint32_t b0, uint32_t b1) {
    asm volatile(
        "mma.sync.aligned.m16n8k8.row.col.f32.tf32.tf32.f32 "
        "{%0,%1,%2,%3}, {%4,%5,%6,%7}, {%8,%9}, {%0,%1,%2,%3};"
        : "+f"(d0), "+f"(d1), "+f"(d2), "+f"(d3)
        : "r"(a0), "r"(a1), "r"(a2), "r"(a3), "r"(b0), "r"(b1));
}

// smem floats: srow[128] | As[2][4][TM][8] | Bs[2][4][BN][8]
#define SMEM_TOTAL (512 + 2 * 4 * TM * 8 * 4 + 2 * 4 * BN * 8 * 4)  // 66048 B

__global__ void __launch_bounds__(THREADS, 2)
tc_gemm_kernel(const float* __restrict__ W,
               const float* __restrict__ bias,
               float* __restrict__ out) {
    const int cx = blockIdx.x;
    if (cx >= g_nchunks) return;
    const int e = g_chunk_e[cx];
    const int pm0 = g_chunk_pm0[cx];
    const int rows = g_chunk_rows[cx];
    const int n0 = blockIdx.y * BN;

    extern __shared__ float sm[];
    int* srow = reinterpret_cast<int*>(sm);         // [128]
    float* As = sm + TM;                            // [2][4][TM][8]
    float* Bs = As + 2 * 4 * TM * 8;                // [2][4][BN][8]

    const int tid = threadIdx.x;
    const int w = tid >> 5, lane = tid & 31;
    const int wm = (w & 1) * 64, wn = (w >> 1) * 64;
    const int grp = lane >> 2, c = lane & 3;

    srow[tid] = g_prow[pm0 + tid];

    // number of live 16-row m-slices for this warp (0..4), warp-uniform
    int live = (rows - wm + 15) >> 4;
    if (live < 0) live = 0;
    if (live > 4) live = 4;

    const float* gW = W + (size_t)e * VOCAB * DM;

    float acc[4][8][4];
    #pragma unroll
    for (int mt = 0; mt < 4; mt++)
        #pragma unroll
        for (int nt = 0; nt < 8; nt++)
            #pragma unroll
            for (int q = 0; q < 4; q++) acc[mt][nt][q] = 0.f;

    float4 pa[4][2];     // A staging: 4 units x 32B
    float4 pb[4][2];     // B staging: 4 units x 32B

    auto load_regs = [&](int kt) {
        const int k0 = kt * BK;
        #pragma unroll
        for (int i = 0; i < 4; i++) {
            int u = tid + THREADS * i;      // < 512: m = u>>2, j = u&3
            int m = u >> 2, j = u & 3;
            const float* ga = g_xs + (size_t)(pm0 + m) * DM + k0 + j * 8;
            pa[i][0] = *reinterpret_cast<const float4*>(ga);
            pa[i][1] = *reinterpret_cast<const float4*>(ga + 4);
        }
        #pragma unroll
        for (int i = 0; i < 4; i++) {
            int u = tid + THREADS * i;      // < 512: n = u>>2, j = u&3
            int n = u >> 2, j = u & 3;
            const float* gb = gW + (size_t)(n0 + n) * DM + k0 + j * 8;
            pb[i][0] = *reinterpret_cast<const float4*>(gb);
            pb[i][1] = *reinterpret_cast<const float4*>(gb + 4);
        }
    };

    auto sts = [&](int st) {
        #pragma unroll
        for (int i = 0; i < 4; i++) {
            int u = tid + THREADS * i;
            int m = u >> 2, j = u & 3;
            float* base = As + (((st * 4 + j) * TM + m) << 3);
            float f0[4] = {pa[i][0].x, pa[i][0].y, pa[i][0].z, pa[i][0].w};
            float f1[4] = {pa[i][1].x, pa[i][1].y, pa[i][1].z, pa[i][1].w};
            #pragma unroll
            for (int cc = 0; cc < 4; cc++)
                *reinterpret_cast<float2*>(base + ((cc ^ j) << 1)) = make_float2(f0[cc], f1[cc]);
        }
        #pragma unroll
        for (int i = 0; i < 4; i++) {
            int u = tid + THREADS * i;
            int n = u >> 2, j = u & 3;
            float* base = Bs + (((st * 4 + j) * BN + n) << 3);
            float f0[4] = {pb[i][0].x, pb[i][0].y, pb[i][0].z, pb[i][0].w};
            float f1[4] = {pb[i][1].x, pb[i][1].y, pb[i][1].z, pb[i][1].w};
            #pragma unroll
            for (int cc = 0; cc < 4; cc++)
                *reinterpret_cast<float2*>(base + ((cc ^ j) << 1)) = make_float2(f0[cc], f1[cc]);
        }
    };

    auto compute = [&](int st) {
        if (live == 0) return;                 // warp-uniform: whole warp idle
        #pragma unroll
        for (int j = 0; j < 4; j++) {
            const int slot2 = ((c ^ j) << 1);
            const float* Aj = As + ((st * 4 + j) * TM << 3);
            const float* Bj = Bs + ((st * 4 + j) * BN << 3);
            uint32_t bf[8][2];
            #pragma unroll
            for (int nt = 0; nt < 8; nt++) {
                int n = wn + nt * 8 + grp;
                float2 bv = *reinterpret_cast<const float2*>(Bj + (n << 3) + slot2);
                bf[nt][0] = cvt_tf32_bits(bv.x);
                bf[nt][1] = cvt_tf32_bits(bv.y);
            }
            #pragma unroll
            for (int mt = 0; mt < 4; mt++) {
                if (mt >= live) break;         // warp-uniform guard: skip dead slices
                int r0 = wm + mt * 16 + grp;
                float2 a0v = *reinterpret_cast<const float2*>(Aj + (r0 << 3) + slot2);
                float2 a1v = *reinterpret_cast<const float2*>(Aj + ((r0 + 8) << 3) + slot2);
                uint32_t a0 = __float_as_uint(a0v.x);
                uint32_t a1 = __float_as_uint(a1v.x);
                uint32_t a2 = __float_as_uint(a0v.y);
                uint32_t a3 = __float_as_uint(a1v.y);
                #pragma unroll
                for (int nt = 0; nt < 8; nt++)
                    mma_tf32(acc[mt][nt][0], acc[mt][nt][1], acc[mt][nt][2], acc[mt][nt][3],
                             a0, a1, a2, a3, bf[nt][0], bf[nt][1]);
            }
        }
    };

    load_regs(0);
    sts(0);
    __syncthreads();

    for (int kt = 0; kt < NKI; kt++) {
        const int st = kt & 1;
        if (kt + 1 < NKI) load_regs(kt + 1);
        compute(st);
        if (kt + 1 < NKI) {
            sts(1 - st);
            __syncthreads();
        }
    }

    // ---- epilogue: bias + scatter float2 stores ----
    if (live > 0) {
        const float* bp = bias + (size_t)e * VOCAB + n0 + wn + c * 2;
        float2 bias2[8];
        #pragma unroll
        for (int nt = 0; nt < 8; nt++)
            bias2[nt] = *reinterpret_cast<const float2*>(bp + nt * 8);

        #pragma unroll
        for (int mt = 0; mt < 4; mt++) {
            if (mt >= live) break;
            const int r0 = wm + mt * 16 + grp;
            const int row0 = srow[r0];
            const int row1 = srow[r0 + 8];
            #pragma unroll
            for (int nt = 0; nt < 8; nt++) {
                const int col = n0 + wn + nt * 8 + c * 2;
                if (row0 >= 0) {
                    float2 o = make_float2(acc[mt][nt][0] + bias2[nt].x,
                                           acc[mt][nt][1] + bias2[nt].y);
                    *reinterpret_cast<float2*>(out + (size_t)row0 * VOCAB + col) = o;
                }
                if (row1 >= 0) {
                    float2 o = make_float2(acc[mt][nt][2] + bias2[nt].x,
                                           acc[mt][nt][3] + bias2[nt].y);
                    *reinterpret_cast<float2*>(out + (size_t)row1 * VOCAB + col) = o;
                }
            }
        }
    }
}

// ---------------------------------------------------------------------------
// Host launch
// ---------------------------------------------------------------------------
extern "C" void kernel_launch(void* const* d_in, const int* in_sizes, int n_in,
                              void* d_out, int out_size) {
    const float*    x    = (const float*)d_in[0];
    const uint32_t* ptr  = (const uint32_t*)d_in[1];
    const float*    W    = (const float*)d_in[2];
    const float*    bias = (const float*)d_in[3];
    float*          out  = (float*)d_out;

    static bool attr_done = false;
    if (!attr_done) {
        cudaFuncSetAttribute(tc_gemm_kernel,
                             cudaFuncAttributeMaxDynamicSharedMemorySize, SMEM_TOTAL);
        attr_done = true;
    }

    group_rows_kernel<<<1, 1024>>>(ptr);
    pack_kernel<<<XSROWS, 128>>>(x);

    dim3 grid(MAXC, VOCAB / BN);   // chunk-fastest -> L2 absorbs W reuse
    tc_gemm_kernel<<<grid, THREADS, SMEM_TOTAL>>>(W, bias, out);
}

// round 16
// speedup vs baseline: 1.0795x; 1.0795x over previous
#include <cuda_runtime.h>
#include <stdint.h>

#define NUM_EXPERTS 8
#define BATCH 4096
#define DM 1024
#define VOCAB 32000

#define TM 128                  // rows per chunk = BM
#define BN 256
#define BK 32
#define NKI (DM / BK)           // 32 k-iterations
#define MAXC 40                 // max chunks: 4096/128 + 8 pad
#define XSROWS (MAXC * TM)      // 5120 padded rows

// ---------------- device scratch (no allocations allowed) ----------------
__device__ int g_rows[BATCH];
__device__ int g_offsets[NUM_EXPERTS + 1];
__device__ int g_chunk_e[MAXC];
__device__ int g_chunk_pm0[MAXC];
__device__ int g_chunk_rows[MAXC];   // valid rows in this chunk (1..128)
__device__ int g_nchunks;
__device__ int g_prow[XSROWS];
__device__ float g_xs[(size_t)XSROWS * DM];  // tf32-rounded gathered x

// ---------------------------------------------------------------------------
// Kernel 1: group rows by expert (ptr % 8), build padded 128-row chunk table.
// Pointer dtype auto-detect (JAX x64-off downcasts int64->int32), as in R3.
// ---------------------------------------------------------------------------
__global__ void group_rows_kernel(const uint32_t* __restrict__ ptr_words) {
    __shared__ int counts[NUM_EXPERTS];
    __shared__ int cursor[NUM_EXPERTS];
    __shared__ int pad_off[NUM_EXPERTS];
    __shared__ int odd_nonzero;
    const int tid = threadIdx.x;

    if (tid == 0) odd_nonzero = 0;
    if (tid < NUM_EXPERTS) counts[tid] = 0;
    __syncthreads();

    int local_nz = 0;
    for (int i = tid; i < BATCH / 2; i += blockDim.x)
        if (ptr_words[2 * i + 1] != 0u) local_nz = 1;
    if (local_nz) atomicOr(&odd_nonzero, 1);
    __syncthreads();
    const bool is_i64 = (odd_nonzero == 0);

    for (int i = tid; i < BATCH; i += blockDim.x) {
        uint32_t v = is_i64 ? ptr_words[2 * i] : ptr_words[i];
        atomicAdd(&counts[v & (NUM_EXPERTS - 1)], 1);
    }
    __syncthreads();
    if (tid == 0) {
        int acc = 0, nc = 0, pbase = 0;
        for (int e = 0; e < NUM_EXPERTS; e++) {
            g_offsets[e] = acc;
            cursor[e] = acc;
            pad_off[e] = pbase;
            int cnt = counts[e];
            int nch = (cnt + TM - 1) / TM;
            for (int j = 0; j < nch; j++) {
                g_chunk_e[nc] = e;
                g_chunk_pm0[nc] = pbase + j * TM;
                int rem = cnt - j * TM;
                g_chunk_rows[nc] = rem > TM ? TM : rem;
                nc++;
            }
            pbase += nch * TM;
            acc += cnt;
        }
        g_offsets[NUM_EXPERTS] = acc;
        g_nchunks = nc;
    }
    __syncthreads();
    for (int i = tid; i < XSROWS; i += blockDim.x) g_prow[i] = -1;
    for (int i = tid; i < BATCH; i += blockDim.x) {
        uint32_t v = is_i64 ? ptr_words[2 * i] : ptr_words[i];
        int pos = atomicAdd(&cursor[v & (NUM_EXPERTS - 1)], 1);
        g_rows[pos] = i;
    }
    __syncthreads();
    for (int i = tid; i < BATCH; i += blockDim.x) {
        int e = 0;
        while (!(i >= g_offsets[e] && i < g_offsets[e + 1])) e++;
        g_prow[pad_off[e] + (i - g_offsets[e])] = g_rows[i];
    }
}

// ---------------------------------------------------------------------------
// Kernel 2: gather + RN-round x rows to tf32 into padded buffer (zeros pad).
// ---------------------------------------------------------------------------
__device__ __forceinline__ float to_tf32_rn(float v) {
    uint32_t b;
    asm("cvt.rna.tf32.f32 %0, %1;" : "=r"(b) : "f"(v));
    return __uint_as_float(b);
}
__device__ __forceinline__ uint32_t cvt_tf32_bits(float v) {
    uint32_t b;
    asm("cvt.rna.tf32.f32 %0, %1;" : "=r"(b) : "f"(v));
    return b;
}

__global__ void pack_kernel(const float* __restrict__ x) {
    const int p = blockIdx.x;
    const int r = g_prow[p];
    float4* dst = reinterpret_cast<float4*>(g_xs + (size_t)p * DM);
    if (r >= 0) {
        const float4* src = reinterpret_cast<const float4*>(x + (size_t)r * DM);
        for (int i = threadIdx.x; i < DM / 4; i += blockDim.x) {
            float4 v = src[i];
            v.x = to_tf32_rn(v.x); v.y = to_tf32_rn(v.y);
            v.z = to_tf32_rn(v.z); v.w = to_tf32_rn(v.w);
            dst[i] = v;
        }
    } else {
        float4 z = make_float4(0.f, 0.f, 0.f, 0.f);
        for (int i = threadIdx.x; i < DM / 4; i += blockDim.x) dst[i] = z;
    }
}

// ---------------------------------------------------------------------------
// Kernel 3: tf32 mma.sync GEMM (champion configuration).
// CTA = 128 rows x 256 vocab cols, 8 warps (2m x 4n), warp tile 64x64,
// BK=32 double-buffered smem with register staging. m-slices (16 rows) past
// the chunk's valid row count skip fragment loads + MMAs (warp-uniform guard).
// ---------------------------------------------------------------------------
__device__ __forceinline__ void mma_tf32(float& d0, float& d1, float& d2, float& d3,
                                         uint32_t a0, uint32_t a1, uint32_t a2, uint32_t a3,
                                         uint32_t b0, uint32_t b1) {
    asm volatile(
        "mma.sync.aligned.m16n8k8.row.col.f32.tf32.tf32.f32 "
        "{%0,%1,%2,%3}, {%4,%5,%6,%7}, {%8,%9}, {%0,%1,%2,%3};"
        : "+f"(d0), "+f"(d1), "+f"(d2), "+f"(d3)
        : "r"(a0), "r"(a1), "r"(a2), "r"(a3), "r"(b0), "r"(b1));
}

#define SMEM_TOTAL (512 + 2 * 4 * TM * 8 * 4 + 2 * 4 * BN * 8 * 4)  // 98816

__global__ void __launch_bounds__(256, 1)
tc_gemm_kernel(const float* __restrict__ W,
               const float* __restrict__ bias,
               float* __restrict__ out) {
    const int cx = blockIdx.x;
    if (cx >= g_nchunks) return;
    const int e = g_chunk_e[cx];
    const int pm0 = g_chunk_pm0[cx];
    const int rows = g_chunk_rows[cx];
    const int n0 = blockIdx.y * BN;

    extern __shared__ float sm[];
    int* srow = reinterpret_cast<int*>(sm);         // [128]
    float* As = sm + TM;                            // [2][4][TM][8]
    float* Bs = As + 2 * 4 * TM * 8;                // [2][4][BN][8]

    const int tid = threadIdx.x;
    const int w = tid >> 5, lane = tid & 31;
    const int wm = (w & 1) * 64, wn = (w >> 1) * 64;
    const int grp = lane >> 2, c = lane & 3;

    if (tid < TM) srow[tid] = g_prow[pm0 + tid];

    // number of live 16-row m-slices for this warp (0..4), warp-uniform
    int live = (rows - wm + 15) >> 4;
    if (live < 0) live = 0;
    if (live > 4) live = 4;

    const float* gW = W + (size_t)e * VOCAB * DM;

    float acc[4][8][4];
    #pragma unroll
    for (int mt = 0; mt < 4; mt++)
        #pragma unroll
        for (int nt = 0; nt < 8; nt++)
            #pragma unroll
            for (int q = 0; q < 4; q++) acc[mt][nt][q] = 0.f;

    float4 pa[2][2];     // A staging: 2 units x 32B
    float4 pb[4][2];     // B staging: 4 units x 32B

    auto load_regs = [&](int kt) {
        const int k0 = kt * BK;
        #pragma unroll
        for (int i = 0; i < 2; i++) {
            int u = tid + 256 * i;
            int m = u >> 2, j = u & 3;
            const float* ga = g_xs + (size_t)(pm0 + m) * DM + k0 + j * 8;
            pa[i][0] = *reinterpret_cast<const float4*>(ga);
            pa[i][1] = *reinterpret_cast<const float4*>(ga + 4);
        }
        #pragma unroll
        for (int i = 0; i < 4; i++) {
            int u = tid + 256 * i;
            int n = u >> 2, j = u & 3;
            const float* gb = gW + (size_t)(n0 + n) * DM + k0 + j * 8;
            pb[i][0] = *reinterpret_cast<const float4*>(gb);
            pb[i][1] = *reinterpret_cast<const float4*>(gb + 4);
        }
    };

    auto sts = [&](int st) {
        #pragma unroll
        for (int i = 0; i < 2; i++) {
            int u = tid + 256 * i;
            int m = u >> 2, j = u & 3;
            float* base = As + (((st * 4 + j) * TM + m) << 3);
            float f0[4] = {pa[i][0].x, pa[i][0].y, pa[i][0].z, pa[i][0].w};
            float f1[4] = {pa[i][1].x, pa[i][1].y, pa[i][1].z, pa[i][1].w};
            #pragma unroll
            for (int cc = 0; cc < 4; cc++)
                *reinterpret_cast<float2*>(base + ((cc ^ j) << 1)) = make_float2(f0[cc], f1[cc]);
        }
        #pragma unroll
        for (int i = 0; i < 4; i++) {
            int u = tid + 256 * i;
            int n = u >> 2, j = u & 3;
            float* base = Bs + (((st * 4 + j) * BN + n) << 3);
            float f0[4] = {pb[i][0].x, pb[i][0].y, pb[i][0].z, pb[i][0].w};
            float f1[4] = {pb[i][1].x, pb[i][1].y, pb[i][1].z, pb[i][1].w};
            #pragma unroll
            for (int cc = 0; cc < 4; cc++)
                *reinterpret_cast<float2*>(base + ((cc ^ j) << 1)) = make_float2(f0[cc], f1[cc]);
        }
    };

    auto compute = [&](int st) {
        if (live == 0) return;                 // warp-uniform: whole warp idle
        #pragma unroll
        for (int j = 0; j < 4; j++) {
            const int slot2 = ((c ^ j) << 1);
            const float* Aj = As + ((st * 4 + j) * TM << 3);
            const float* Bj = Bs + ((st * 4 + j) * BN << 3);
            uint32_t bf[8][2];
            #pragma unroll
            for (int nt = 0; nt < 8; nt++) {
                int n = wn + nt * 8 + grp;
                float2 bv = *reinterpret_cast<const float2*>(Bj + (n << 3) + slot2);
                bf[nt][0] = cvt_tf32_bits(bv.x);
                bf[nt][1] = cvt_tf32_bits(bv.y);
            }
            #pragma unroll
            for (int mt = 0; mt < 4; mt++) {
                if (mt >= live) break;         // warp-uniform guard: skip dead slices
                int r0 = wm + mt * 16 + grp;
                float2 a0v = *reinterpret_cast<const float2*>(Aj + (r0 << 3) + slot2);
                float2 a1v = *reinterpret_cast<const float2*>(Aj + ((r0 + 8) << 3) + slot2);
                uint32_t a0 = __float_as_uint(a0v.x);
                uint32_t a1 = __float_as_uint(a1v.x);
                uint32_t a2 = __float_as_uint(a0v.y);
                uint32_t a3 = __float_as_uint(a1v.y);
                #pragma unroll
                for (int nt = 0; nt < 8; nt++)
                    mma_tf32(acc[mt][nt][0], acc[mt][nt][1], acc[mt][nt][2], acc[mt][nt][3],
                             a0, a1, a2, a3, bf[nt][0], bf[nt][1]);
            }
        }
    };

    load_regs(0);
    sts(0);
    __syncthreads();

    for (int kt = 0; kt < NKI; kt++) {
        const int st = kt & 1;
        if (kt + 1 < NKI) load_regs(kt + 1);
        compute(st);
        if (kt + 1 < NKI) {
            sts(1 - st);
            __syncthreads();
        }
    }

    // ---- epilogue: bias + scatter float2 stores ----
    if (live > 0) {
        const float* bp = bias + (size_t)e * VOCAB + n0 + wn + c * 2;
        float2 bias2[8];
        #pragma unroll
        for (int nt = 0; nt < 8; nt++)
            bias2[nt] = *reinterpret_cast<const float2*>(bp + nt * 8);

        #pragma unroll
        for (int mt = 0; mt < 4; mt++) {
            if (mt >= live) break;
            const int r0 = wm + mt * 16 + grp;
            const int row0 = srow[r0];
            const int row1 = srow[r0 + 8];
            #pragma unroll
            for (int nt = 0; nt < 8; nt++) {
                const int col = n0 + wn + nt * 8 + c * 2;
                if (row0 >= 0) {
                    float2 o = make_float2(acc[mt][nt][0] + bias2[nt].x,
                                           acc[mt][nt][1] + bias2[nt].y);
                    *reinterpret_cast<float2*>(out + (size_t)row0 * VOCAB + col) = o;
                }
                if (row1 >= 0) {
                    float2 o = make_float2(acc[mt][nt][2] + bias2[nt].x,
                                           acc[mt][nt][3] + bias2[nt].y);
                    *reinterpret_cast<float2*>(out + (size_t)row1 * VOCAB + col) = o;
                }
            }
        }
    }
}

// ---------------------------------------------------------------------------
// Host launch
// ---------------------------------------------------------------------------
extern "C" void kernel_launch(void* const* d_in, const int* in_sizes, int n_in,
                              void* d_out, int out_size) {
    const float*    x    = (const float*)d_in[0];
    const uint32_t* ptr  = (const uint32_t*)d_in[1];
    const float*    W    = (const float*)d_in[2];
    const float*    bias = (const float*)d_in[3];
    float*          out  = (float*)d_out;

    static bool attr_done = false;
    if (!attr_done) {
        cudaFuncSetAttribute(tc_gemm_kernel,
                             cudaFuncAttributeMaxDynamicSharedMemorySize, SMEM_TOTAL);
        attr_done = true;
    }

    group_rows_kernel<<<1, 1024>>>(ptr);
    pack_kernel<<<XSROWS, 128>>>(x);

    dim3 grid(MAXC, VOCAB / BN);   // chunk-fastest -> L2 absorbs W reuse
    tc_gemm_kernel<<<grid, 256, SMEM_TOTAL>>>(W, bias, out);
}

// round 17
// speedup vs baseline: 1.0808x; 1.0013x over previous
#include <cuda_runtime.h>
#include <stdint.h>

#define NUM_EXPERTS 8
#define BATCH 4096
#define DM 1024
#define VOCAB 32000

#define TM 128                  // rows per chunk = BM
#define BN 256
#define BK 32
#define NKI (DM / BK)           // 32 k-iterations
#define MAXC 40                 // max chunks: 4096/128 + 8 pad
#define XSROWS (MAXC * TM)      // 5120 padded rows

// ---------------- device scratch (no allocations allowed) ----------------
__device__ int g_rows[BATCH];
__device__ int g_offsets[NUM_EXPERTS + 1];
__device__ int g_chunk_e[MAXC];
__device__ int g_chunk_pm0[MAXC];
__device__ int g_chunk_rows[MAXC];   // valid rows in this chunk (1..128)
__device__ int g_nchunks;
__device__ int g_prow[XSROWS];
__device__ float g_xs[(size_t)XSROWS * DM];  // tf32-rounded gathered x

// ---------------------------------------------------------------------------
// Kernel 1: group rows by expert (ptr % 8), build padded 128-row chunk table.
// Pointer dtype auto-detect (JAX x64-off downcasts int64->int32), as in R3.
// ---------------------------------------------------------------------------
__global__ void group_rows_kernel(const uint32_t* __restrict__ ptr_words) {
    __shared__ int counts[NUM_EXPERTS];
    __shared__ int cursor[NUM_EXPERTS];
    __shared__ int pad_off[NUM_EXPERTS];
    __shared__ int odd_nonzero;
    const int tid = threadIdx.x;

    if (tid == 0) odd_nonzero = 0;
    if (tid < NUM_EXPERTS) counts[tid] = 0;
    __syncthreads();

    int local_nz = 0;
    for (int i = tid; i < BATCH / 2; i += blockDim.x)
        if (ptr_words[2 * i + 1] != 0u) local_nz = 1;
    if (local_nz) atomicOr(&odd_nonzero, 1);
    __syncthreads();
    const bool is_i64 = (odd_nonzero == 0);

    for (int i = tid; i < BATCH; i += blockDim.x) {
        uint32_t v = is_i64 ? ptr_words[2 * i] : ptr_words[i];
        atomicAdd(&counts[v & (NUM_EXPERTS - 1)], 1);
    }
    __syncthreads();
    if (tid == 0) {
        int acc = 0, nc = 0, pbase = 0;
        for (int e = 0; e < NUM_EXPERTS; e++) {
            g_offsets[e] = acc;
            cursor[e] = acc;
            pad_off[e] = pbase;
            int cnt = counts[e];
            int nch = (cnt + TM - 1) / TM;
            for (int j = 0; j < nch; j++) {
                g_chunk_e[nc] = e;
                g_chunk_pm0[nc] = pbase + j * TM;
                int rem = cnt - j * TM;
                g_chunk_rows[nc] = rem > TM ? TM : rem;
                nc++;
            }
            pbase += nch * TM;
            acc += cnt;
        }
        g_offsets[NUM_EXPERTS] = acc;
        g_nchunks = nc;
    }
    __syncthreads();
    for (int i = tid; i < XSROWS; i += blockDim.x) g_prow[i] = -1;
    for (int i = tid; i < BATCH; i += blockDim.x) {
        uint32_t v = is_i64 ? ptr_words[2 * i] : ptr_words[i];
        int pos = atomicAdd(&cursor[v & (NUM_EXPERTS - 1)], 1);
        g_rows[pos] = i;
    }
    __syncthreads();
    for (int i = tid; i < BATCH; i += blockDim.x) {
        int e = 0;
        while (!(i >= g_offsets[e] && i < g_offsets[e + 1])) e++;
        g_prow[pad_off[e] + (i - g_offsets[e])] = g_rows[i];
    }
}

// ---------------------------------------------------------------------------
// Kernel 2: gather + RN-round x rows to tf32 into padded buffer (zeros pad).
// ---------------------------------------------------------------------------
__device__ __forceinline__ float to_tf32_rn(float v) {
    uint32_t b;
    asm("cvt.rna.tf32.f32 %0, %1;" : "=r"(b) : "f"(v));
    return __uint_as_float(b);
}
__device__ __forceinline__ uint32_t cvt_tf32_bits(float v) {
    uint32_t b;
    asm("cvt.rna.tf32.f32 %0, %1;" : "=r"(b) : "f"(v));
    return b;
}

__global__ void pack_kernel(const float* __restrict__ x) {
    const int p = blockIdx.x;
    const int r = g_prow[p];
    float4* dst = reinterpret_cast<float4*>(g_xs + (size_t)p * DM);
    if (r >= 0) {
        const float4* src = reinterpret_cast<const float4*>(x + (size_t)r * DM);
        for (int i = threadIdx.x; i < DM / 4; i += blockDim.x) {
            float4 v = src[i];
            v.x = to_tf32_rn(v.x); v.y = to_tf32_rn(v.y);
            v.z = to_tf32_rn(v.z); v.w = to_tf32_rn(v.w);
            dst[i] = v;
        }
    } else {
        float4 z = make_float4(0.f, 0.f, 0.f, 0.f);
        for (int i = threadIdx.x; i < DM / 4; i += blockDim.x) dst[i] = z;
    }
}

// ---------------------------------------------------------------------------
// Kernel 3: tf32 mma.sync GEMM (champion configuration).
// CTA = 128 rows x 256 vocab cols, 8 warps (2m x 4n), warp tile 64x64,
// BK=32 double-buffered smem with register staging. m-slices (16 rows) past
// the chunk's valid row count skip fragment loads + MMAs (warp-uniform guard).
// ---------------------------------------------------------------------------
__device__ __forceinline__ void mma_tf32(float& d0, float& d1, float& d2, float& d3,
                                         uint32_t a0, uint32_t a1, uint32_t a2, uint32_t a3,
                                         uint32_t b0, uint32_t b1) {
    asm volatile(
        "mma.sync.aligned.m16n8k8.row.col.f32.tf32.tf32.f32 "
        "{%0,%1,%2,%3}, {%4,%5,%6,%7}, {%8,%9}, {%0,%1,%2,%3};"
        : "+f"(d0), "+f"(d1), "+f"(d2), "+f"(d3)
        : "r"(a0), "r"(a1), "r"(a2), "r"(a3), "r"(b0), "r"(b1));
}

#define SMEM_TOTAL (512 + 2 * 4 * TM * 8 * 4 + 2 * 4 * BN * 8 * 4)  // 98816

__global__ void __launch_bounds__(256, 1)
tc_gemm_kernel(const float* __restrict__ W,
               const float* __restrict__ bias,
               float* __restrict__ out) {
    const int cx = blockIdx.x;
    if (cx >= g_nchunks) return;
    const int e = g_chunk_e[cx];
    const int pm0 = g_chunk_pm0[cx];
    const int rows = g_chunk_rows[cx];
    const int n0 = blockIdx.y * BN;

    extern __shared__ float sm[];
    int* srow = reinterpret_cast<int*>(sm);         // [128]
    float* As = sm + TM;                            // [2][4][TM][8]
    float* Bs = As + 2 * 4 * TM * 8;                // [2][4][BN][8]

    const int tid = threadIdx.x;
    const int w = tid >> 5, lane = tid & 31;
    const int wm = (w & 1) * 64, wn = (w >> 1) * 64;
    const int grp = lane >> 2, c = lane & 3;

    if (tid < TM) srow[tid] = g_prow[pm0 + tid];

    // number of live 16-row m-slices for this warp (0..4), warp-uniform
    int live = (rows - wm + 15) >> 4;
    if (live < 0) live = 0;
    if (live > 4) live = 4;

    const float* gW = W + (size_t)e * VOCAB * DM;

    float acc[4][8][4];
    #pragma unroll
    for (int mt = 0; mt < 4; mt++)
        #pragma unroll
        for (int nt = 0; nt < 8; nt++)
            #pragma unroll
            for (int q = 0; q < 4; q++) acc[mt][nt][q] = 0.f;

    float4 pa[2][2];     // A staging: 2 units x 32B
    float4 pb[4][2];     // B staging: 4 units x 32B

    auto load_regs = [&](int kt) {
        const int k0 = kt * BK;
        #pragma unroll
        for (int i = 0; i < 2; i++) {
            int u = tid + 256 * i;
            int m = u >> 2, j = u & 3;
            const float* ga = g_xs + (size_t)(pm0 + m) * DM + k0 + j * 8;
            pa[i][0] = *reinterpret_cast<const float4*>(ga);
            pa[i][1] = *reinterpret_cast<const float4*>(ga + 4);
        }
        #pragma unroll
        for (int i = 0; i < 4; i++) {
            int u = tid + 256 * i;
            int n = u >> 2, j = u & 3;
            const float* gb = gW + (size_t)(n0 + n) * DM + k0 + j * 8;
            pb[i][0] = *reinterpret_cast<const float4*>(gb);
            pb[i][1] = *reinterpret_cast<const float4*>(gb + 4);
        }
    };

    auto sts = [&](int st) {
        #pragma unroll
        for (int i = 0; i < 2; i++) {
            int u = tid + 256 * i;
            int m = u >> 2, j = u & 3;
            float* base = As + (((st * 4 + j) * TM + m) << 3);
            float f0[4] = {pa[i][0].x, pa[i][0].y, pa[i][0].z, pa[i][0].w};
            float f1[4] = {pa[i][1].x, pa[i][1].y, pa[i][1].z, pa[i][1].w};
            #pragma unroll
            for (int cc = 0; cc < 4; cc++)
                *reinterpret_cast<float2*>(base + ((cc ^ j) << 1)) = make_float2(f0[cc], f1[cc]);
        }
        #pragma unroll
        for (int i = 0; i < 4; i++) {
            int u = tid + 256 * i;
            int n = u >> 2, j = u & 3;
            float* base = Bs + (((st * 4 + j) * BN + n) << 3);
            float f0[4] = {pb[i][0].x, pb[i][0].y, pb[i][0].z, pb[i][0].w};
            float f1[4] = {pb[i][1].x, pb[i][1].y, pb[i][1].z, pb[i][1].w};
            #pragma unroll
            for (int cc = 0; cc < 4; cc++)
                *reinterpret_cast<float2*>(base + ((cc ^ j) << 1)) = make_float2(f0[cc], f1[cc]);
        }
    };

    auto compute = [&](int st) {
        if (live == 0) return;                 // warp-uniform: whole warp idle
        #pragma unroll
        for (int j = 0; j < 4; j++) {
            const int slot2 = ((c ^ j) << 1);
            const float* Aj = As + ((st * 4 + j) * TM << 3);
            const float* Bj = Bs + ((st * 4 + j) * BN << 3);
            uint32_t bf[8][2];
            #pragma unroll
            for (int nt = 0; nt < 8; nt++) {
                int n = wn + nt * 8 + grp;
                float2 bv = *reinterpret_cast<const float2*>(Bj + (n << 3) + slot2);
                bf[nt][0] = cvt_tf32_bits(bv.x);
                bf[nt][1] = cvt_tf32_bits(bv.y);
            }
            #pragma unroll
            for (int mt = 0; mt < 4; mt++) {
                if (mt >= live) break;         // warp-uniform guard: skip dead slices
                int r0 = wm + mt * 16 + grp;
                float2 a0v = *reinterpret_cast<const float2*>(Aj + (r0 << 3) + slot2);
                float2 a1v = *reinterpret_cast<const float2*>(Aj + ((r0 + 8) << 3) + slot2);
                uint32_t a0 = __float_as_uint(a0v.x);
                uint32_t a1 = __float_as_uint(a1v.x);
                uint32_t a2 = __float_as_uint(a0v.y);
                uint32_t a3 = __float_as_uint(a1v.y);
                #pragma unroll
                for (int nt = 0; nt < 8; nt++)
                    mma_tf32(acc[mt][nt][0], acc[mt][nt][1], acc[mt][nt][2], acc[mt][nt][3],
                             a0, a1, a2, a3, bf[nt][0], bf[nt][1]);
            }
        }
    };

    load_regs(0);
    sts(0);
    __syncthreads();

    for (int kt = 0; kt < NKI; kt++) {
        const int st = kt & 1;
        if (kt + 1 < NKI) load_regs(kt + 1);
        compute(st);
        if (kt + 1 < NKI) {
            sts(1 - st);
            __syncthreads();
        }
    }

    // ---- epilogue: bias + scatter float2 stores ----
    if (live > 0) {
        const float* bp = bias + (size_t)e * VOCAB + n0 + wn + c * 2;
        float2 bias2[8];
        #pragma unroll
        for (int nt = 0; nt < 8; nt++)
            bias2[nt] = *reinterpret_cast<const float2*>(bp + nt * 8);

        #pragma unroll
        for (int mt = 0; mt < 4; mt++) {
            if (mt >= live) break;
            const int r0 = wm + mt * 16 + grp;
            const int row0 = srow[r0];
            const int row1 = srow[r0 + 8];
            #pragma unroll
            for (int nt = 0; nt < 8; nt++) {
                const int col = n0 + wn + nt * 8 + c * 2;
                if (row0 >= 0) {
                    float2 o = make_float2(acc[mt][nt][0] + bias2[nt].x,
                                           acc[mt][nt][1] + bias2[nt].y);
                    *reinterpret_cast<float2*>(out + (size_t)row0 * VOCAB + col) = o;
                }
                if (row1 >= 0) {
                    float2 o = make_float2(acc[mt][nt][2] + bias2[nt].x,
                                           acc[mt][nt][3] + bias2[nt].y);
                    *reinterpret_cast<float2*>(out + (size_t)row1 * VOCAB + col) = o;
                }
            }
        }
    }
}

// ---------------------------------------------------------------------------
// Host launch
// ---------------------------------------------------------------------------
extern "C" void kernel_launch(void* const* d_in, const int* in_sizes, int n_in,
                              void* d_out, int out_size) {
    const float*    x    = (const float*)d_in[0];
    const uint32_t* ptr  = (const uint32_t*)d_in[1];
    const float*    W    = (const float*)d_in[2];
    const float*    bias = (const float*)d_in[3];
    float*          out  = (float*)d_out;

    static bool attr_done = false;
    if (!attr_done) {
        cudaFuncSetAttribute(tc_gemm_kernel,
                             cudaFuncAttributeMaxDynamicSharedMemorySize, SMEM_TOTAL);
        attr_done = true;
    }

    group_rows_kernel<<<1, 1024>>>(ptr);
    pack_kernel<<<XSROWS, 128>>>(x);

    dim3 grid(MAXC, VOCAB / BN);   // chunk-fastest -> L2 absorbs W reuse
    tc_gemm_kernel<<<grid, 256, SMEM_TOTAL>>>(W, bias, out);
}